// round 11
// baseline (speedup 1.0000x reference)
#include <cuda_runtime.h>
#include <cuda_fp16.h>
#include <cuda_bf16.h>
#include <cstdint>

#define N_NODES 100000
#define N_EDGES 1600000
#define D 128
#define LEAKY 0.2f
#define SCAN_B 98          // 98 * 1024 = 100352 >= N_NODES
#define SCAN_T 1024

// Padded row stride for smem/gmem bf16 tiles: 136 bf16 = 272 B (16B-aligned).
// Fragment LDS bank = (4*row + lanequad) mod 32 -> conflict-free.
#define RSTRIDE_E 136
#define RSTRIDE_B 272

// Scratch (allocation-free rule: __device__ globals)
__device__ __half g_h16[(size_t)N_NODES * D];      // 25.6 MB (fp16 h)
__device__ float g_score_t[N_NODES];
__device__ float g_score_s[N_NODES];
__device__ int   g_cnt[N_NODES];
__device__ int   g_row_ptr[N_NODES + 1];
__device__ int   g_cursor[N_NODES];
__device__ int   g_blocksum[SCAN_B];
__device__ int   g_blockoff[SCAN_B];
__device__ int2  g_csr[N_EDGES];                   // {src, float_bits(e)}
__device__ __nv_bfloat16 g_wt_hi[128 * RSTRIDE_E]; // Wt hi, padded [n][k]
__device__ __nv_bfloat16 g_wt_lo[128 * RSTRIDE_E]; // Wt lo

__device__ __forceinline__ int clamp_idx(int v) {
    v = v < 0 ? 0 : v;
    return v >= N_NODES ? N_NODES - 1 : v;
}

__device__ __forceinline__ uint32_t pack_bf16(__nv_bfloat16 a, __nv_bfloat16 b) {
    __nv_bfloat162 p = {a, b};
    return *(uint32_t*)&p;
}

// ---------------------------------------------------------------------------
// W prep: Wt_hi/lo[n][k] = split(W[k][n]) into padded global buffers.
// ---------------------------------------------------------------------------
__global__ void wprep_kernel(const float* __restrict__ W) {
    int k = blockIdx.x;            // 0..127
    int n = threadIdx.x;           // 0..127
    float w = W[k * 128 + n];      // coalesced in n
    __nv_bfloat16 hi = __float2bfloat16(w);
    __nv_bfloat16 lo = __float2bfloat16(w - __bfloat162float(hi));
    g_wt_hi[n * RSTRIDE_E + k] = hi;
    g_wt_lo[n * RSTRIDE_E + k] = lo;
}

// ---------------------------------------------------------------------------
// zero the per-target edge counters
// ---------------------------------------------------------------------------
__global__ void zero_cnt_kernel() {
    int i = blockIdx.x * blockDim.x + threadIdx.x;
    if (i < N_NODES) g_cnt[i] = 0;
}

// ---------------------------------------------------------------------------
// histogram of target degrees
// ---------------------------------------------------------------------------
__global__ void hist_kernel(const int* __restrict__ edges) {
    int i = blockIdx.x * blockDim.x + threadIdx.x;
    if (i >= N_EDGES) return;
    int2 e2 = ((const int2*)edges)[i];       // {tgt, src}
    atomicAdd(&g_cnt[clamp_idx(e2.x)], 1);
}

// ---------------------------------------------------------------------------
// exclusive scan, 3 kernels
// ---------------------------------------------------------------------------
__global__ void scan1_kernel() {
    __shared__ int sdata[SCAN_T];
    int tid = threadIdx.x;
    int gid = blockIdx.x * SCAN_T + tid;
    int v = (gid < N_NODES) ? g_cnt[gid] : 0;
    sdata[tid] = v;
    __syncthreads();
    #pragma unroll
    for (int off = 1; off < SCAN_T; off <<= 1) {
        int x = (tid >= off) ? sdata[tid - off] : 0;
        __syncthreads();
        sdata[tid] += x;
        __syncthreads();
    }
    if (gid < N_NODES) g_row_ptr[gid] = sdata[tid] - v;   // exclusive
    if (tid == SCAN_T - 1) g_blocksum[blockIdx.x] = sdata[tid];
}

__global__ void scan2_kernel() {
    __shared__ int sdata[128];
    int tid = threadIdx.x;
    int v = (tid < SCAN_B) ? g_blocksum[tid] : 0;
    sdata[tid] = v;
    __syncthreads();
    #pragma unroll
    for (int off = 1; off < 128; off <<= 1) {
        int x = (tid >= off) ? sdata[tid - off] : 0;
        __syncthreads();
        sdata[tid] += x;
        __syncthreads();
    }
    if (tid < SCAN_B) g_blockoff[tid] = sdata[tid] - v;   // exclusive
}

__global__ void scan3_kernel() {
    int tid = threadIdx.x;
    int gid = blockIdx.x * SCAN_T + tid;
    if (gid < N_NODES) {
        int v = g_row_ptr[gid] + g_blockoff[blockIdx.x];
        g_row_ptr[gid] = v;
        g_cursor[gid]  = v;
    }
    if (gid == 0) g_row_ptr[N_NODES] = N_EDGES;
}

// ---------------------------------------------------------------------------
// HMMA GEMM: H = X @ W via mma.sync m16n8k16 bf16, hi/lo split (3 terms).
// CTA: 256 threads (8 warps), tile M=128 x N=128 x K=128.
// Warp grid 4x2: warp (wm, wn) owns rows [wm*32,+32) x cols [wn*64,+64).
// 8 warps/SM (2 per SMSP) hides MMA/LDS latency that 4 warps could not.
// ---------------------------------------------------------------------------
#define MMA3(accj, A0,A1,A2,A3, B0,B1) \
    asm volatile( \
        "mma.sync.aligned.m16n8k16.row.col.f32.bf16.bf16.f32 " \
        "{%0,%1,%2,%3}, {%4,%5,%6,%7}, {%8,%9}, {%0,%1,%2,%3};" \
        : "+f"(accj[0]), "+f"(accj[1]), "+f"(accj[2]), "+f"(accj[3]) \
        : "r"(A0), "r"(A1), "r"(A2), "r"(A3), "r"(B0), "r"(B1))

__global__ void __launch_bounds__(256)
gemm_mma_kernel(const float* __restrict__ X,
                const float* __restrict__ KA) {
    extern __shared__ char smem[];
    float* sKA = (float*)smem;                       // 256 floats = 1KB
    float* sSc = (float*)(smem + 1024);              // [2][128][2] = 2KB
    char* sAh = smem + 3072;                         // 128 x 272B = 34816
    char* sAl = sAh + 128 * RSTRIDE_B;               // 34816
    char* sBh = sAl + 128 * RSTRIDE_B;               // 34816
    char* sBl = sBh + 128 * RSTRIDE_B;               // 34816

    const int tid  = threadIdx.x;
    const int w    = tid >> 5;
    const int lane = tid & 31;
    const int wm   = w >> 1;          // 0..3: row quarter
    const int wn   = w & 1;           // 0..1: col half
    const int rowBase = blockIdx.x * 128;

    // KA -> smem
    if (tid < 128) { sKA[tid] = KA[tid]; sKA[128 + tid] = KA[128 + tid]; }

    // B tiles: straight copy of precomputed padded Wt hi/lo (2176 uint4 each)
    {
        const uint4* srcH = (const uint4*)g_wt_hi;
        const uint4* srcL = (const uint4*)g_wt_lo;
        uint4* dstH = (uint4*)sBh;
        uint4* dstL = (uint4*)sBl;
        #pragma unroll
        for (int i = tid; i < 128 * RSTRIDE_E / 8; i += 256) {
            dstH[i] = srcH[i];
            dstL[i] = srcL[i];
        }
    }

    // A tiles: load X rows, split to bf16 hi/lo (128 rows x 32 float4)
    {
        const float4* X4 = (const float4*)X;
        #pragma unroll
        for (int i = tid; i < 128 * 32; i += 256) {
            int r = i >> 5, c4 = i & 31;
            int row = rowBase + r;
            float4 v = make_float4(0.f, 0.f, 0.f, 0.f);
            if (row < N_NODES) v = X4[(size_t)row * 32 + c4];
            __nv_bfloat16 h0 = __float2bfloat16(v.x);
            __nv_bfloat16 h1 = __float2bfloat16(v.y);
            __nv_bfloat16 h2 = __float2bfloat16(v.z);
            __nv_bfloat16 h3 = __float2bfloat16(v.w);
            __nv_bfloat16 l0 = __float2bfloat16(v.x - __bfloat162float(h0));
            __nv_bfloat16 l1 = __float2bfloat16(v.y - __bfloat162float(h1));
            __nv_bfloat16 l2 = __float2bfloat16(v.z - __bfloat162float(h2));
            __nv_bfloat16 l3 = __float2bfloat16(v.w - __bfloat162float(h3));
            int off = r * RSTRIDE_B + c4 * 8;
            *(uint2*)(sAh + off) = make_uint2(pack_bf16(h0, h1), pack_bf16(h2, h3));
            *(uint2*)(sAl + off) = make_uint2(pack_bf16(l0, l1), pack_bf16(l2, l3));
        }
    }
    __syncthreads();

    const int r = lane >> 2;      // 0..7
    const int c = lane & 3;       // 0..3
    // A fragment offsets for the warp's two m16 tiles (rows wm*32 .. wm*32+31)
    const int aoff0 = (wm * 32 + r) * RSTRIDE_B + c * 4;
    const int aoff1 = aoff0 + 16 * RSTRIDE_B;
    // B fragment base for the warp's 8 j-tiles (cols wn*64 ..)
    const int boff0 = (wn * 8) * 8 * RSTRIDE_B + r * RSTRIDE_B + c * 4;

    float acc[2][8][4];
    #pragma unroll
    for (int mt = 0; mt < 2; mt++)
        #pragma unroll
        for (int j = 0; j < 8; j++) {
            acc[mt][j][0] = 0.f; acc[mt][j][1] = 0.f;
            acc[mt][j][2] = 0.f; acc[mt][j][3] = 0.f;
        }

    #pragma unroll
    for (int s = 0; s < 8; s++) {
        const int ak0 = aoff0 + s * 32;
        const int ak1 = aoff1 + s * 32;
        uint32_t ah[2][4], al[2][4];
        ah[0][0] = *(const uint32_t*)(sAh + ak0);
        ah[0][1] = *(const uint32_t*)(sAh + ak0 + 8 * RSTRIDE_B);
        ah[0][2] = *(const uint32_t*)(sAh + ak0 + 16);
        ah[0][3] = *(const uint32_t*)(sAh + ak0 + 8 * RSTRIDE_B + 16);
        al[0][0] = *(const uint32_t*)(sAl + ak0);
        al[0][1] = *(const uint32_t*)(sAl + ak0 + 8 * RSTRIDE_B);
        al[0][2] = *(const uint32_t*)(sAl + ak0 + 16);
        al[0][3] = *(const uint32_t*)(sAl + ak0 + 8 * RSTRIDE_B + 16);
        ah[1][0] = *(const uint32_t*)(sAh + ak1);
        ah[1][1] = *(const uint32_t*)(sAh + ak1 + 8 * RSTRIDE_B);
        ah[1][2] = *(const uint32_t*)(sAh + ak1 + 16);
        ah[1][3] = *(const uint32_t*)(sAh + ak1 + 8 * RSTRIDE_B + 16);
        al[1][0] = *(const uint32_t*)(sAl + ak1);
        al[1][1] = *(const uint32_t*)(sAl + ak1 + 8 * RSTRIDE_B);
        al[1][2] = *(const uint32_t*)(sAl + ak1 + 16);
        al[1][3] = *(const uint32_t*)(sAl + ak1 + 8 * RSTRIDE_B + 16);

        #pragma unroll
        for (int j = 0; j < 8; j++) {
            const int bk = boff0 + j * 8 * RSTRIDE_B + s * 32;
            uint32_t bh0 = *(const uint32_t*)(sBh + bk);
            uint32_t bh1 = *(const uint32_t*)(sBh + bk + 16);
            uint32_t bl0 = *(const uint32_t*)(sBl + bk);
            uint32_t bl1 = *(const uint32_t*)(sBl + bk + 16);
            #pragma unroll
            for (int mt = 0; mt < 2; mt++) {
                MMA3(acc[mt][j], ah[mt][0], ah[mt][1], ah[mt][2], ah[mt][3], bh0, bh1);
                MMA3(acc[mt][j], ah[mt][0], ah[mt][1], ah[mt][2], ah[mt][3], bl0, bl1);
                MMA3(acc[mt][j], al[mt][0], al[mt][1], al[mt][2], al[mt][3], bh0, bh1);
            }
        }
    }

    // Epilogue: lane owns rows (base+r, base+r+8) per m-tile,
    // cols wn*64 + j*8 + c*2 (+1). Partial scores over the warp's 64 cols.
    #pragma unroll
    for (int mt = 0; mt < 2; mt++) {
        int lrow0 = wm * 32 + mt * 16 + r;     // local row in [0,128)
        int lrow1 = lrow0 + 8;
        int row0 = rowBase + lrow0;
        int row1 = rowBase + lrow1;
        bool v0 = row0 < N_NODES, v1 = row1 < N_NODES;
        float st0 = 0.f, ss0 = 0.f, st1 = 0.f, ss1 = 0.f;

        #pragma unroll
        for (int j = 0; j < 8; j++) {
            int col = wn * 64 + j * 8 + c * 2;
            float kt0 = sKA[col], kt1 = sKA[col + 1];
            float ks0 = sKA[128 + col], ks1 = sKA[128 + col + 1];
            if (v0) {
                __half2 p = __floats2half2_rn(acc[mt][j][0], acc[mt][j][1]);
                *(uint32_t*)(g_h16 + (size_t)row0 * D + col) = *(uint32_t*)&p;
                st0 += acc[mt][j][0] * kt0 + acc[mt][j][1] * kt1;
                ss0 += acc[mt][j][0] * ks0 + acc[mt][j][1] * ks1;
            }
            if (v1) {
                __half2 p = __floats2half2_rn(acc[mt][j][2], acc[mt][j][3]);
                *(uint32_t*)(g_h16 + (size_t)row1 * D + col) = *(uint32_t*)&p;
                st1 += acc[mt][j][2] * kt0 + acc[mt][j][3] * kt1;
                ss1 += acc[mt][j][2] * ks0 + acc[mt][j][3] * ss1 * 0.f + acc[mt][j][3] * ks1;
            }
        }

        // quad reduce (lanes 4q..4q+3 share rows)
        #pragma unroll
        for (int m = 1; m <= 2; m <<= 1) {
            st0 += __shfl_xor_sync(0xffffffff, st0, m);
            ss0 += __shfl_xor_sync(0xffffffff, ss0, m);
            st1 += __shfl_xor_sync(0xffffffff, st1, m);
            ss1 += __shfl_xor_sync(0xffffffff, ss1, m);
        }
        if (c == 0) {
            // partials: sSc[wn][lrow][0..1]
            sSc[(wn * 128 + lrow0) * 2 + 0] = st0;
            sSc[(wn * 128 + lrow0) * 2 + 1] = ss0;
            sSc[(wn * 128 + lrow1) * 2 + 0] = st1;
            sSc[(wn * 128 + lrow1) * 2 + 1] = ss1;
        }
    }
    __syncthreads();

    // combine the two column-half partials
    if (tid < 128) {
        int row = rowBase + tid;
        if (row < N_NODES) {
            g_score_t[row] = sSc[tid * 2 + 0] + sSc[(128 + tid) * 2 + 0];
            g_score_s[row] = sSc[tid * 2 + 1] + sSc[(128 + tid) * 2 + 1];
        }
    }
}

// ---------------------------------------------------------------------------
// fill CSR: per edge compute e = exp(clip(leaky(st[t]+ss[s]))), pack {src,e}
// ---------------------------------------------------------------------------
__global__ void fill_kernel(const int* __restrict__ edges) {
    int i = blockIdx.x * blockDim.x + threadIdx.x;
    if (i >= N_EDGES) return;
    int2 e2 = ((const int2*)edges)[i];       // {tgt, src}
    int t = clamp_idx(e2.x);
    int s = clamp_idx(e2.y);
    float x = g_score_t[t] + g_score_s[s];
    x = (x > 0.0f) ? x : LEAKY * x;          // leaky_relu
    x = fminf(fmaxf(x, -2.0f), 2.0f);        // clip
    float e = __expf(x);
    int pos = atomicAdd(&g_cursor[t], 1);
    g_csr[pos] = make_int2(s, __float_as_int(e));
}

// ---------------------------------------------------------------------------
// node gather: one warp per target node, fp16 h rows (256B), 4-wide MLP.
// ---------------------------------------------------------------------------
__global__ void node_gather_kernel(float* __restrict__ out) {
    int gw = (blockIdx.x * blockDim.x + threadIdx.x) >> 5;
    int lane = threadIdx.x & 31;
    if (gw >= N_NODES) return;

    int beg = g_row_ptr[gw];
    int end = g_row_ptr[gw + 1];

    const uint2* H2 = (const uint2*)g_h16;   // 4 halves per lane per row
    float4 acc = make_float4(0.f, 0.f, 0.f, 0.f);
    float se = 0.f;

    int j = beg;
    for (; j + 4 <= end; j += 4) {
        int2 p0 = g_csr[j];
        int2 p1 = g_csr[j + 1];
        int2 p2 = g_csr[j + 2];
        int2 p3 = g_csr[j + 3];
        uint2 v0 = H2[(size_t)p0.x * 32 + lane];
        uint2 v1 = H2[(size_t)p1.x * 32 + lane];
        uint2 v2 = H2[(size_t)p2.x * 32 + lane];
        uint2 v3 = H2[(size_t)p3.x * 32 + lane];
        float e0 = __int_as_float(p0.y);
        float e1 = __int_as_float(p1.y);
        float e2 = __int_as_float(p2.y);
        float e3 = __int_as_float(p3.y);
        {
            float2 a = __half22float2(*(__half2*)&v0.x);
            float2 b = __half22float2(*(__half2*)&v0.y);
            acc.x += e0 * a.x; acc.y += e0 * a.y; acc.z += e0 * b.x; acc.w += e0 * b.y;
        }
        {
            float2 a = __half22float2(*(__half2*)&v1.x);
            float2 b = __half22float2(*(__half2*)&v1.y);
            acc.x += e1 * a.x; acc.y += e1 * a.y; acc.z += e1 * b.x; acc.w += e1 * b.y;
        }
        {
            float2 a = __half22float2(*(__half2*)&v2.x);
            float2 b = __half22float2(*(__half2*)&v2.y);
            acc.x += e2 * a.x; acc.y += e2 * a.y; acc.z += e2 * b.x; acc.w += e2 * b.y;
        }
        {
            float2 a = __half22float2(*(__half2*)&v3.x);
            float2 b = __half22float2(*(__half2*)&v3.y);
            acc.x += e3 * a.x; acc.y += e3 * a.y; acc.z += e3 * b.x; acc.w += e3 * b.y;
        }
        se += e0 + e1 + e2 + e3;
    }
    for (; j < end; ++j) {
        int2 p = g_csr[j];
        float e = __int_as_float(p.y);
        uint2 v = H2[(size_t)p.x * 32 + lane];
        float2 a = __half22float2(*(__half2*)&v.x);
        float2 b = __half22float2(*(__half2*)&v.y);
        acc.x += e * a.x; acc.y += e * a.y; acc.z += e * b.x; acc.w += e * b.y;
        se += e;
    }

    float inv = 1.0f / (se + 1e-9f);
    ((float4*)out)[(size_t)gw * 32 + lane] =
        make_float4(acc.x * inv, acc.y * inv, acc.z * inv, acc.w * inv);
}

// ---------------------------------------------------------------------------
extern "C" void kernel_launch(void* const* d_in, const int* in_sizes, int n_in,
                              void* d_out, int out_size) {
    const float* node_states = (const float*)d_in[0];
    const int*   edges       = (const int*)d_in[1];   // int32 (jax x64 disabled)
    const float* kern        = (const float*)d_in[2];
    const float* kern_attn   = (const float*)d_in[3];
    float* out = (float*)d_out;

    (void)in_sizes; (void)n_in; (void)out_size;

    const int GEMM_SMEM = 3072 + 4 * (128 * RSTRIDE_B);   // 142336 bytes
    cudaFuncSetAttribute(gemm_mma_kernel,
                         cudaFuncAttributeMaxDynamicSharedMemorySize,
                         GEMM_SMEM);

    // CSR build prologue + W split (independent of GEMM)
    zero_cnt_kernel<<<SCAN_B, SCAN_T>>>();
    wprep_kernel<<<128, 128>>>(kern);
    hist_kernel<<<(N_EDGES + 255) / 256, 256>>>(edges);

    // HMMA GEMM as 4th launch (lands in the ncu capture slot)
    gemm_mma_kernel<<<(N_NODES + 127) / 128, 256, GEMM_SMEM>>>(node_states, kern_attn);

    scan1_kernel<<<SCAN_B, SCAN_T>>>();
    scan2_kernel<<<1, 128>>>();
    scan3_kernel<<<SCAN_B, SCAN_T>>>();

    // per-edge scores into CSR slots
    fill_kernel<<<(N_EDGES + 255) / 256, 256>>>(edges);

    // warp-per-node gather + normalize + store (writes every output row)
    long long total = (long long)N_NODES * 32;
    node_gather_kernel<<<(unsigned)((total + 255) / 256), 256>>>(out);
}

// round 12
// speedup vs baseline: 1.4194x; 1.4194x over previous
#include <cuda_runtime.h>
#include <cuda_fp16.h>
#include <cuda_bf16.h>
#include <cstdint>

#define N_NODES 100000
#define N_EDGES 1600000
#define D 128
#define LEAKY 0.2f
#define SCAN_B 98          // 98 * 1024 = 100352 >= N_NODES
#define SCAN_T 1024

// Padded row stride for smem/gmem bf16 tiles: 136 bf16 = 272 B (16B-aligned).
// Fragment LDS bank = (4*row + lanequad) mod 32 -> conflict-free.
#define RSTRIDE_E 136
#define RSTRIDE_B 272

// Scratch (allocation-free rule: __device__ globals)
__device__ __half g_h16[(size_t)N_NODES * D];      // 25.6 MB (fp16 h)
__device__ float g_score_t[N_NODES];
__device__ float g_score_s[N_NODES];
__device__ int   g_cnt[N_NODES];
__device__ int   g_row_ptr[N_NODES + 1];
__device__ int   g_cursor[N_NODES];
__device__ int   g_blocksum[SCAN_B];
__device__ int   g_blockoff[SCAN_B];
__device__ int2  g_csr[N_EDGES];                   // {src, float_bits(e)}
__device__ __nv_bfloat16 g_wt_hi[128 * RSTRIDE_E]; // Wt hi, padded [n][k]
__device__ __nv_bfloat16 g_wt_lo[128 * RSTRIDE_E]; // Wt lo

__device__ __forceinline__ int clamp_idx(int v) {
    v = v < 0 ? 0 : v;
    return v >= N_NODES ? N_NODES - 1 : v;
}

__device__ __forceinline__ uint32_t pack_bf16(__nv_bfloat16 a, __nv_bfloat16 b) {
    __nv_bfloat162 p = {a, b};
    return *(uint32_t*)&p;
}

// ---------------------------------------------------------------------------
// W prep: Wt_hi/lo[n][k] = split(W[k][n]) into padded global buffers.
// ---------------------------------------------------------------------------
__global__ void wprep_kernel(const float* __restrict__ W) {
    int k = blockIdx.x;            // 0..127
    int n = threadIdx.x;           // 0..127
    float w = W[k * 128 + n];      // coalesced in n
    __nv_bfloat16 hi = __float2bfloat16(w);
    __nv_bfloat16 lo = __float2bfloat16(w - __bfloat162float(hi));
    g_wt_hi[n * RSTRIDE_E + k] = hi;
    g_wt_lo[n * RSTRIDE_E + k] = lo;
}

// ---------------------------------------------------------------------------
// zero per-target counters + score accumulators (scores now atomically built)
// ---------------------------------------------------------------------------
__global__ void zero_cnt_kernel() {
    int i = blockIdx.x * blockDim.x + threadIdx.x;
    if (i < N_NODES) {
        g_cnt[i] = 0;
        g_score_t[i] = 0.f;
        g_score_s[i] = 0.f;
    }
}

// ---------------------------------------------------------------------------
// histogram of target degrees
// ---------------------------------------------------------------------------
__global__ void hist_kernel(const int* __restrict__ edges) {
    int i = blockIdx.x * blockDim.x + threadIdx.x;
    if (i >= N_EDGES) return;
    int2 e2 = ((const int2*)edges)[i];       // {tgt, src}
    atomicAdd(&g_cnt[clamp_idx(e2.x)], 1);
}

// ---------------------------------------------------------------------------
// exclusive scan, 3 kernels
// ---------------------------------------------------------------------------
__global__ void scan1_kernel() {
    __shared__ int sdata[SCAN_T];
    int tid = threadIdx.x;
    int gid = blockIdx.x * SCAN_T + tid;
    int v = (gid < N_NODES) ? g_cnt[gid] : 0;
    sdata[tid] = v;
    __syncthreads();
    #pragma unroll
    for (int off = 1; off < SCAN_T; off <<= 1) {
        int x = (tid >= off) ? sdata[tid - off] : 0;
        __syncthreads();
        sdata[tid] += x;
        __syncthreads();
    }
    if (gid < N_NODES) g_row_ptr[gid] = sdata[tid] - v;   // exclusive
    if (tid == SCAN_T - 1) g_blocksum[blockIdx.x] = sdata[tid];
}

__global__ void scan2_kernel() {
    __shared__ int sdata[128];
    int tid = threadIdx.x;
    int v = (tid < SCAN_B) ? g_blocksum[tid] : 0;
    sdata[tid] = v;
    __syncthreads();
    #pragma unroll
    for (int off = 1; off < 128; off <<= 1) {
        int x = (tid >= off) ? sdata[tid - off] : 0;
        __syncthreads();
        sdata[tid] += x;
        __syncthreads();
    }
    if (tid < SCAN_B) g_blockoff[tid] = sdata[tid] - v;   // exclusive
}

__global__ void scan3_kernel() {
    int tid = threadIdx.x;
    int gid = blockIdx.x * SCAN_T + tid;
    if (gid < N_NODES) {
        int v = g_row_ptr[gid] + g_blockoff[blockIdx.x];
        g_row_ptr[gid] = v;
        g_cursor[gid]  = v;
    }
    if (gid == 0) g_row_ptr[N_NODES] = N_EDGES;
}

// ---------------------------------------------------------------------------
// HMMA GEMM: H = X @ W via mma.sync m16n8k16 bf16, hi/lo split (3 terms).
// CTA: 128 threads (4 warps), tile M=64 x N=64 x K=128; gridDim.y=2 splits N.
// smem ~70KB -> 3 CTAs/SM = 12 warps (3/SMSP) to hide MMA/LDS latency.
// Warp grid 2x2 of M32 x N32 tiles. Scores: per-CTA partials -> atomicAdd.
// ---------------------------------------------------------------------------
#define MMA3(accj, A0,A1,A2,A3, B0,B1) \
    asm volatile( \
        "mma.sync.aligned.m16n8k16.row.col.f32.bf16.bf16.f32 " \
        "{%0,%1,%2,%3}, {%4,%5,%6,%7}, {%8,%9}, {%0,%1,%2,%3};" \
        : "+f"(accj[0]), "+f"(accj[1]), "+f"(accj[2]), "+f"(accj[3]) \
        : "r"(A0), "r"(A1), "r"(A2), "r"(A3), "r"(B0), "r"(B1))

__global__ void __launch_bounds__(128)
gemm_mma_kernel(const float* __restrict__ X,
                const float* __restrict__ KA) {
    extern __shared__ char smem[];
    float* sKA = (float*)smem;                       // 256 floats = 1KB
    float* sSc = (float*)(smem + 1024);              // [2][64][2] = 1KB
    char* sAh = smem + 2048;                         // 64 x 272B = 17408
    char* sAl = sAh + 64 * RSTRIDE_B;                // 17408
    char* sBh = sAl + 64 * RSTRIDE_B;                // 17408
    char* sBl = sBh + 64 * RSTRIDE_B;                // 17408

    const int tid  = threadIdx.x;
    const int w    = tid >> 5;
    const int lane = tid & 31;
    const int wm   = w >> 1;          // 0..1: row half
    const int wn   = w & 1;           // 0..1: col half (within CTA's 64 cols)
    const int rowBase = blockIdx.x * 64;
    const int ny   = blockIdx.y;      // 0..1: which 64-col half of N

    // KA -> smem (all 256; epilogue uses global col)
    if (tid < 128) { sKA[tid] = KA[tid]; sKA[128 + tid] = KA[128 + tid]; }

    // B tiles: copy this CTA's 64 n-rows of padded Wt hi/lo (1088 uint4 each)
    {
        const uint4* srcH = (const uint4*)(g_wt_hi + ny * 64 * RSTRIDE_E);
        const uint4* srcL = (const uint4*)(g_wt_lo + ny * 64 * RSTRIDE_E);
        uint4* dstH = (uint4*)sBh;
        uint4* dstL = (uint4*)sBl;
        #pragma unroll
        for (int i = tid; i < 64 * RSTRIDE_E / 8; i += 128) {
            dstH[i] = srcH[i];
            dstL[i] = srcL[i];
        }
    }

    // A tiles: load X rows, split to bf16 hi/lo (64 rows x 32 float4)
    {
        const float4* X4 = (const float4*)X;
        #pragma unroll
        for (int i = tid; i < 64 * 32; i += 128) {
            int r = i >> 5, c4 = i & 31;
            int row = rowBase + r;
            float4 v = make_float4(0.f, 0.f, 0.f, 0.f);
            if (row < N_NODES) v = X4[(size_t)row * 32 + c4];
            __nv_bfloat16 h0 = __float2bfloat16(v.x);
            __nv_bfloat16 h1 = __float2bfloat16(v.y);
            __nv_bfloat16 h2 = __float2bfloat16(v.z);
            __nv_bfloat16 h3 = __float2bfloat16(v.w);
            __nv_bfloat16 l0 = __float2bfloat16(v.x - __bfloat162float(h0));
            __nv_bfloat16 l1 = __float2bfloat16(v.y - __bfloat162float(h1));
            __nv_bfloat16 l2 = __float2bfloat16(v.z - __bfloat162float(h2));
            __nv_bfloat16 l3 = __float2bfloat16(v.w - __bfloat162float(h3));
            int off = r * RSTRIDE_B + c4 * 8;
            *(uint2*)(sAh + off) = make_uint2(pack_bf16(h0, h1), pack_bf16(h2, h3));
            *(uint2*)(sAl + off) = make_uint2(pack_bf16(l0, l1), pack_bf16(l2, l3));
        }
    }
    __syncthreads();

    const int r = lane >> 2;      // 0..7
    const int c = lane & 3;       // 0..3
    // A fragment offsets for the warp's two m16 tiles (rows wm*32 .. wm*32+31)
    const int aoff0 = (wm * 32 + r) * RSTRIDE_B + c * 4;
    const int aoff1 = aoff0 + 16 * RSTRIDE_B;
    // B fragment base for the warp's 4 j-tiles (CTA-local cols wn*32 ..)
    const int boff0 = (wn * 4) * 8 * RSTRIDE_B + r * RSTRIDE_B + c * 4;

    float acc[2][4][4];
    #pragma unroll
    for (int mt = 0; mt < 2; mt++)
        #pragma unroll
        for (int j = 0; j < 4; j++) {
            acc[mt][j][0] = 0.f; acc[mt][j][1] = 0.f;
            acc[mt][j][2] = 0.f; acc[mt][j][3] = 0.f;
        }

    #pragma unroll
    for (int s = 0; s < 8; s++) {
        const int ak0 = aoff0 + s * 32;
        const int ak1 = aoff1 + s * 32;
        uint32_t ah[2][4], al[2][4];
        ah[0][0] = *(const uint32_t*)(sAh + ak0);
        ah[0][1] = *(const uint32_t*)(sAh + ak0 + 8 * RSTRIDE_B);
        ah[0][2] = *(const uint32_t*)(sAh + ak0 + 16);
        ah[0][3] = *(const uint32_t*)(sAh + ak0 + 8 * RSTRIDE_B + 16);
        al[0][0] = *(const uint32_t*)(sAl + ak0);
        al[0][1] = *(const uint32_t*)(sAl + ak0 + 8 * RSTRIDE_B);
        al[0][2] = *(const uint32_t*)(sAl + ak0 + 16);
        al[0][3] = *(const uint32_t*)(sAl + ak0 + 8 * RSTRIDE_B + 16);
        ah[1][0] = *(const uint32_t*)(sAh + ak1);
        ah[1][1] = *(const uint32_t*)(sAh + ak1 + 8 * RSTRIDE_B);
        ah[1][2] = *(const uint32_t*)(sAh + ak1 + 16);
        ah[1][3] = *(const uint32_t*)(sAh + ak1 + 8 * RSTRIDE_B + 16);
        al[1][0] = *(const uint32_t*)(sAl + ak1);
        al[1][1] = *(const uint32_t*)(sAl + ak1 + 8 * RSTRIDE_B);
        al[1][2] = *(const uint32_t*)(sAl + ak1 + 16);
        al[1][3] = *(const uint32_t*)(sAl + ak1 + 8 * RSTRIDE_B + 16);

        #pragma unroll
        for (int j = 0; j < 4; j++) {
            const int bk = boff0 + j * 8 * RSTRIDE_B + s * 32;
            uint32_t bh0 = *(const uint32_t*)(sBh + bk);
            uint32_t bh1 = *(const uint32_t*)(sBh + bk + 16);
            uint32_t bl0 = *(const uint32_t*)(sBl + bk);
            uint32_t bl1 = *(const uint32_t*)(sBl + bk + 16);
            #pragma unroll
            for (int mt = 0; mt < 2; mt++) {
                MMA3(acc[mt][j], ah[mt][0], ah[mt][1], ah[mt][2], ah[mt][3], bh0, bh1);
                MMA3(acc[mt][j], ah[mt][0], ah[mt][1], ah[mt][2], ah[mt][3], bl0, bl1);
                MMA3(acc[mt][j], al[mt][0], al[mt][1], al[mt][2], al[mt][3], bh0, bh1);
            }
        }
    }

    // Epilogue: lane owns rows (base+r, base+r+8) per m-tile,
    // CTA-local cols wn*32 + j*8 + c*2 (+1); global col adds ny*64.
    #pragma unroll
    for (int mt = 0; mt < 2; mt++) {
        int lrow0 = wm * 32 + mt * 16 + r;     // local row in [0,64)
        int lrow1 = lrow0 + 8;
        int row0 = rowBase + lrow0;
        int row1 = rowBase + lrow1;
        bool v0 = row0 < N_NODES, v1 = row1 < N_NODES;
        float st0 = 0.f, ss0 = 0.f, st1 = 0.f, ss1 = 0.f;

        #pragma unroll
        for (int j = 0; j < 4; j++) {
            int gcol = ny * 64 + wn * 32 + j * 8 + c * 2;
            float kt0 = sKA[gcol], kt1 = sKA[gcol + 1];
            float ks0 = sKA[128 + gcol], ks1 = sKA[128 + gcol + 1];
            if (v0) {
                __half2 p = __floats2half2_rn(acc[mt][j][0], acc[mt][j][1]);
                *(uint32_t*)(g_h16 + (size_t)row0 * D + gcol) = *(uint32_t*)&p;
                st0 += acc[mt][j][0] * kt0 + acc[mt][j][1] * kt1;
                ss0 += acc[mt][j][0] * ks0 + acc[mt][j][1] * ks1;
            }
            if (v1) {
                __half2 p = __floats2half2_rn(acc[mt][j][2], acc[mt][j][3]);
                *(uint32_t*)(g_h16 + (size_t)row1 * D + gcol) = *(uint32_t*)&p;
                st1 += acc[mt][j][2] * kt0 + acc[mt][j][3] * kt1;
                ss1 += acc[mt][j][2] * ks0 + acc[mt][j][3] * ks1;
            }
        }

        // quad reduce (lanes 4q..4q+3 share rows)
        #pragma unroll
        for (int m = 1; m <= 2; m <<= 1) {
            st0 += __shfl_xor_sync(0xffffffff, st0, m);
            ss0 += __shfl_xor_sync(0xffffffff, ss0, m);
            st1 += __shfl_xor_sync(0xffffffff, st1, m);
            ss1 += __shfl_xor_sync(0xffffffff, ss1, m);
        }
        if (c == 0) {
            sSc[(wn * 64 + lrow0) * 2 + 0] = st0;
            sSc[(wn * 64 + lrow0) * 2 + 1] = ss0;
            sSc[(wn * 64 + lrow1) * 2 + 0] = st1;
            sSc[(wn * 64 + lrow1) * 2 + 1] = ss1;
        }
    }
    __syncthreads();

    // combine the CTA's two column-half partials, then atomicAdd (N split
    // across gridDim.y means two CTAs contribute to each row's score).
    if (tid < 64) {
        int row = rowBase + tid;
        if (row < N_NODES) {
            float t = sSc[tid * 2 + 0] + sSc[(64 + tid) * 2 + 0];
            float s = sSc[tid * 2 + 1] + sSc[(64 + tid) * 2 + 1];
            atomicAdd(&g_score_t[row], t);
            atomicAdd(&g_score_s[row], s);
        }
    }
}

// ---------------------------------------------------------------------------
// fill CSR: per edge compute e = exp(clip(leaky(st[t]+ss[s]))), pack {src,e}
// ---------------------------------------------------------------------------
__global__ void fill_kernel(const int* __restrict__ edges) {
    int i = blockIdx.x * blockDim.x + threadIdx.x;
    if (i >= N_EDGES) return;
    int2 e2 = ((const int2*)edges)[i];       // {tgt, src}
    int t = clamp_idx(e2.x);
    int s = clamp_idx(e2.y);
    float x = g_score_t[t] + g_score_s[s];
    x = (x > 0.0f) ? x : LEAKY * x;          // leaky_relu
    x = fminf(fmaxf(x, -2.0f), 2.0f);        // clip
    float e = __expf(x);
    int pos = atomicAdd(&g_cursor[t], 1);
    g_csr[pos] = make_int2(s, __float_as_int(e));
}

// ---------------------------------------------------------------------------
// node gather: one warp per target node, fp16 h rows (256B), 8-wide MLP.
// ---------------------------------------------------------------------------
__global__ void node_gather_kernel(float* __restrict__ out) {
    int gw = (blockIdx.x * blockDim.x + threadIdx.x) >> 5;
    int lane = threadIdx.x & 31;
    if (gw >= N_NODES) return;

    int beg = g_row_ptr[gw];
    int end = g_row_ptr[gw + 1];

    const uint2* H2 = (const uint2*)g_h16;   // 4 halves per lane per row
    float4 acc = make_float4(0.f, 0.f, 0.f, 0.f);
    float se = 0.f;

    int j = beg;
    for (; j + 8 <= end; j += 8) {
        int2 p[8];
        uint2 v[8];
        #pragma unroll
        for (int q = 0; q < 8; q++) p[q] = g_csr[j + q];
        #pragma unroll
        for (int q = 0; q < 8; q++) v[q] = H2[(size_t)p[q].x * 32 + lane];
        #pragma unroll
        for (int q = 0; q < 8; q++) {
            float e = __int_as_float(p[q].y);
            float2 a = __half22float2(*(__half2*)&v[q].x);
            float2 b = __half22float2(*(__half2*)&v[q].y);
            acc.x += e * a.x; acc.y += e * a.y;
            acc.z += e * b.x; acc.w += e * b.y;
            se += e;
        }
    }
    for (; j < end; ++j) {
        int2 p = g_csr[j];
        float e = __int_as_float(p.y);
        uint2 v = H2[(size_t)p.x * 32 + lane];
        float2 a = __half22float2(*(__half2*)&v.x);
        float2 b = __half22float2(*(__half2*)&v.y);
        acc.x += e * a.x; acc.y += e * a.y; acc.z += e * b.x; acc.w += e * b.y;
        se += e;
    }

    float inv = 1.0f / (se + 1e-9f);
    ((float4*)out)[(size_t)gw * 32 + lane] =
        make_float4(acc.x * inv, acc.y * inv, acc.z * inv, acc.w * inv);
}

// ---------------------------------------------------------------------------
extern "C" void kernel_launch(void* const* d_in, const int* in_sizes, int n_in,
                              void* d_out, int out_size) {
    const float* node_states = (const float*)d_in[0];
    const int*   edges       = (const int*)d_in[1];   // int32 (jax x64 disabled)
    const float* kern        = (const float*)d_in[2];
    const float* kern_attn   = (const float*)d_in[3];
    float* out = (float*)d_out;

    (void)in_sizes; (void)n_in; (void)out_size;

    const int GEMM_SMEM = 2048 + 4 * (64 * RSTRIDE_B);   // 71680 bytes -> 3 CTA/SM
    cudaFuncSetAttribute(gemm_mma_kernel,
                         cudaFuncAttributeMaxDynamicSharedMemorySize,
                         GEMM_SMEM);

    // CSR build prologue + W split (independent of GEMM)
    zero_cnt_kernel<<<SCAN_B, SCAN_T>>>();
    wprep_kernel<<<128, 128>>>(kern);
    hist_kernel<<<(N_EDGES + 255) / 256, 256>>>(edges);

    // HMMA GEMM as 4th launch (lands in the ncu capture slot)
    dim3 ggrid((N_NODES + 63) / 64, 2);
    gemm_mma_kernel<<<ggrid, 128, GEMM_SMEM>>>(node_states, kern_attn);

    scan1_kernel<<<SCAN_B, SCAN_T>>>();
    scan2_kernel<<<1, 128>>>();
    scan3_kernel<<<SCAN_B, SCAN_T>>>();

    // per-edge scores into CSR slots
    fill_kernel<<<(N_EDGES + 255) / 256, 256>>>(edges);

    // warp-per-node gather + normalize + store (writes every output row)
    long long total = (long long)N_NODES * 32;
    node_gather_kernel<<<(unsigned)((total + 255) / 256), 256>>>(out);
}